// round 16
// baseline (speedup 1.0000x reference)
#include <cuda_runtime.h>
#include <cuda_fp16.h>
#include <math.h>
#include <stdint.h>

#define N_NODES 20000
#define N_EDGES 640000
#define FDIM 6
#define D 128
#define D4 512
#define STEPS 11          // 1 + DEPTH
#define K0 384            // layer0 K: agg(128)+feat(128)+h0(128)
#define K12 256           // layers 1,2 K: h_prev(128)+h_self(128)

#define BM 128
#define BN 128
#define BK 64
#define NSTAGES 3
#define LDA (BK + 8)              // 72 halfs: 144B row stride (16B multiple)
#define STAGE_HALFS ((BM + BN) * LDA)
#define SMEM_BYTES (NSTAGES * STAGE_HALFS * 2)   // 110592 > C staging 67584
#define MGROUPS 157               // row-tile groups

// ----------------------------------------------------------------------------
// Scratch (device globals; ping-pong parity buffers; activations in fp16)
// ----------------------------------------------------------------------------
__device__ __half g_A0[2][N_NODES * K0];    // [agg | feat | h0]
__device__ __half g_A1[2][N_NODES * K12];   // [h0 | h1]
__device__ __half g_A2[2][N_NODES * K12];   // [h1 | h2]
__device__ float  g_c[3][N_NODES * D];
__device__ __half g_W0[D4 * K0];            // interleaved-gate rows, fp16
__device__ __half g_W1[D4 * K12];
__device__ __half g_W2[D4 * K12];
__device__ float  g_bias_il[3 * D4];        // interleaved (bih+bhh)
__device__ int    g_deg[N_NODES];
__device__ int    g_rowstart[N_NODES + 1];
__device__ int    g_cursor[N_NODES];
__device__ int    g_csr[N_EDGES];
__device__ int    g_lsync[MGROUPS * 2];     // per-(row-group, layer) barrier counters

// ----------------------------------------------------------------------------
// Init / preprocessing
// ----------------------------------------------------------------------------
__global__ void zero_all_kernel() {
    int idx = blockIdx.x * blockDim.x + threadIdx.x;
    int stride = gridDim.x * blockDim.x;
    int* a0 = (int*)&g_A0[0][0];
    int* a1 = (int*)&g_A1[0][0];
    int* a2 = (int*)&g_A2[0][0];
    for (int i = idx; i < N_NODES * K0 / 2; i += stride)  a0[i] = 0;
    for (int i = idx; i < N_NODES * K12 / 2; i += stride) a1[i] = 0;
    for (int i = idx; i < N_NODES * K12 / 2; i += stride) a2[i] = 0;
    for (int i = idx; i < 3 * N_NODES * D; i += stride) (&g_c[0][0])[i] = 0.0f;
    for (int i = idx; i < N_NODES; i += stride) { g_deg[i] = 0; g_cursor[i] = 0; }
}

// One kernel builds all interleaved fp16 weights + combined bias.
// Interleave: row r = 4*d + g  <-  old row g*128+d; K = [Wih | Whh]
__device__ __forceinline__ void build_one_w(__half* dst, const float* Wih,
                                            const float* Whh, int Kin, int idx) {
    int K = Kin + D;
    int r = idx / K, k = idx % K;
    int d = r >> 2, g = r & 3;
    int orow = g * D + d;
    float v = (k < Kin) ? Wih[orow * Kin + k] : Whh[orow * D + (k - Kin)];
    dst[idx] = __float2half_rn(v);
}

__global__ void build_all_kernel(const float* __restrict__ Wih0,
                                 const float* __restrict__ Wih_rest,
                                 const float* __restrict__ Whh,
                                 const float* __restrict__ bih,
                                 const float* __restrict__ bhh) {
    const int N0 = D4 * K0;             // 196608
    const int N1 = D4 * K12;            // 131072
    int idx = blockIdx.x * blockDim.x + threadIdx.x;
    if (idx < N0) {
        build_one_w(g_W0, Wih0, Whh, 2 * D, idx);
    } else if (idx < N0 + N1) {
        build_one_w(g_W1, Wih_rest, Whh + D4 * D, D, idx - N0);
    } else if (idx < N0 + 2 * N1) {
        build_one_w(g_W2, Wih_rest + D4 * D, Whh + 2 * D4 * D, D, idx - N0 - N1);
    } else if (idx < N0 + 2 * N1 + 3 * D4) {
        int i = idx - N0 - 2 * N1;
        int l = i >> 9, r = i & 511;
        int d = r >> 2, g = r & 3;
        int o = l * D4 + g * D + d;
        g_bias_il[i] = bih[o] + bhh[o];
    }
}
#define BUILD_TOTAL (D4 * K0 + 2 * D4 * K12 + 3 * D4)

// feat = relu(features @ W_in + b_in) -> g_A0[0] cols [128,256), fp16
__global__ void init_feat_kernel(const float* __restrict__ features,
                                 const float* __restrict__ W_in,
                                 const float* __restrict__ b_in) {
    __shared__ float sW[FDIM * D];
    __shared__ float sb[D];
    int t = threadIdx.x;
    for (int i = t; i < FDIM * D; i += blockDim.x) sW[i] = W_in[i];
    for (int i = t; i < D; i += blockDim.x) sb[i] = b_in[i];
    __syncthreads();
    int idx = blockIdx.x * blockDim.x + t;
    if (idx >= N_NODES * D) return;
    int n = idx >> 7;
    int d = idx & (D - 1);
    float acc = sb[d];
#pragma unroll
    for (int f = 0; f < FDIM; f++) acc += features[n * FDIM + f] * sW[f * D + d];
    g_A0[0][n * K0 + D + d] = __float2half_rn(fmaxf(acc, 0.0f));
}

__global__ void count_deg_kernel(const int* __restrict__ dst) {
    int e = blockIdx.x * blockDim.x + threadIdx.x;
    if (e < N_EDGES) atomicAdd(&g_deg[dst[e]], 1);
}

__global__ void scan_deg_kernel() {
    __shared__ int sh[1024];
    int t = threadIdx.x;
    int carry = 0;
    for (int base = 0; base < N_NODES; base += 1024) {
        int v = (base + t < N_NODES) ? g_deg[base + t] : 0;
        sh[t] = v;
        __syncthreads();
        for (int off = 1; off < 1024; off <<= 1) {
            int x = (t >= off) ? sh[t - off] : 0;
            __syncthreads();
            sh[t] += x;
            __syncthreads();
        }
        if (base + t < N_NODES) g_rowstart[base + t] = carry + sh[t] - v;
        int blocktotal = sh[1023];
        __syncthreads();
        carry += blocktotal;
    }
    if (t == 0) g_rowstart[N_NODES] = carry;
}

__global__ void fill_csr_kernel(const int* __restrict__ src,
                                const int* __restrict__ dst) {
    int e = blockIdx.x * blockDim.x + threadIdx.x;
    if (e < N_EDGES) {
        int d = dst[e];
        int pos = atomicAdd(&g_cursor[d], 1);
        g_csr[g_rowstart[d] + pos] = src[e];
    }
}

// ----------------------------------------------------------------------------
// Mean aggregation (fp16 in/out, fp32 accum): one warp per node.
// Also zeroes the layer-barrier counters for the following fused step kernel.
// ----------------------------------------------------------------------------
__global__ void agg_kernel(int p) {
    if (blockIdx.x == 0) {
        for (int i = threadIdx.x; i < MGROUPS * 2; i += blockDim.x) g_lsync[i] = 0;
    }
    const __half* A0r = g_A0[p];
    __half* A0w = g_A0[p];
    int warp = (blockIdx.x * blockDim.x + threadIdx.x) >> 5;
    int lane = threadIdx.x & 31;
    if (warp >= N_NODES) return;
    int s0 = g_rowstart[warp];
    int s1 = g_rowstart[warp + 1];
    float ax = 0.f, ay = 0.f, az = 0.f, aw = 0.f;
    int coff = D + lane * 4;
    int e = s0;
    for (; e + 4 <= s1; e += 4) {
        int n0 = g_csr[e + 0];
        int n1 = g_csr[e + 1];
        int n2 = g_csr[e + 2];
        int n3 = g_csr[e + 3];
        uint2 r0 = *reinterpret_cast<const uint2*>(&A0r[(size_t)n0 * K0 + coff]);
        uint2 r1 = *reinterpret_cast<const uint2*>(&A0r[(size_t)n1 * K0 + coff]);
        uint2 r2 = *reinterpret_cast<const uint2*>(&A0r[(size_t)n2 * K0 + coff]);
        uint2 r3 = *reinterpret_cast<const uint2*>(&A0r[(size_t)n3 * K0 + coff]);
#pragma unroll
        for (int q = 0; q < 4; q++) {
            uint2 rr = (q == 0) ? r0 : (q == 1) ? r1 : (q == 2) ? r2 : r3;
            __half2 p0 = *reinterpret_cast<__half2*>(&rr.x);
            __half2 p1 = *reinterpret_cast<__half2*>(&rr.y);
            float2 f0 = __half22float2(p0);
            float2 f1 = __half22float2(p1);
            ax += f0.x; ay += f0.y; az += f1.x; aw += f1.y;
        }
    }
    for (; e < s1; e++) {
        int s = g_csr[e];
        uint2 raw = *reinterpret_cast<const uint2*>(&A0r[(size_t)s * K0 + coff]);
        __half2 p0 = *reinterpret_cast<__half2*>(&raw.x);
        __half2 p1 = *reinterpret_cast<__half2*>(&raw.y);
        float2 f0 = __half22float2(p0);
        float2 f1 = __half22float2(p1);
        ax += f0.x; ay += f0.y; az += f1.x; aw += f1.y;
    }
    float inv = (s1 > s0) ? 1.0f / (float)(s1 - s0) : 0.0f;
    __half2 o0 = __floats2half2_rn(ax * inv, ay * inv);
    __half2 o1 = __floats2half2_rn(az * inv, aw * inv);
    uint2 outw;
    outw.x = *reinterpret_cast<uint32_t*>(&o0);
    outw.y = *reinterpret_cast<uint32_t*>(&o1);
    *reinterpret_cast<uint2*>(&A0w[warp * K0 + lane * 4]) = outw;
}

// ----------------------------------------------------------------------------
// Fused 3-layer step kernel: grid (4, 157) — x = column block, y = row group.
// Inter-layer dependency is row-local: the 4 column-CTAs of one row group
// synchronize via a per-(group,layer) counter; adjacent block indices keep
// them co-resident so the spin cannot deadlock.
// ----------------------------------------------------------------------------
__device__ __forceinline__ float sigmoidf_(float x) { return 1.0f / (1.0f + expf(-x)); }

__device__ __forceinline__ void cp_async16(uint32_t saddr, const void* gaddr, int srcsize) {
    asm volatile("cp.async.cg.shared.global [%0], [%1], 16, %2;"
                 :: "r"(saddr), "l"(gaddr), "r"(srcsize));
}

__device__ __forceinline__ void ldmatrix_x4(uint32_t& r0, uint32_t& r1,
                                            uint32_t& r2, uint32_t& r3,
                                            uint32_t addr) {
    asm volatile("ldmatrix.sync.aligned.m8n8.x4.shared.b16 {%0,%1,%2,%3}, [%4];"
                 : "=r"(r0), "=r"(r1), "=r"(r2), "=r"(r3) : "r"(addr));
}

extern __shared__ __align__(16) char smem_raw[];

__global__ __launch_bounds__(256, 2)
void step3_kernel(int p) {
    int tid = threadIdx.x;
    int lane = tid & 31, warp = tid >> 5;
    int wr = warp >> 1, wc = warp & 1;          // warp grid 4(m) x 2(n)
    int bm = blockIdx.y * BM, bn = blockIdx.x * BN;
    int q = p ^ 1;
    uint32_t smem_u32 = (uint32_t)__cvta_generic_to_shared(smem_raw);

    int lmat_m = lane & 7;
    int lmat_id = lane >> 3;
    int a_mrow[2], b_nrow[4];
#pragma unroll
    for (int ii = 0; ii < 2; ii++) a_mrow[ii] = wr * 32 + ii * 16 + (lmat_id & 1) * 8 + lmat_m;
#pragma unroll
    for (int jj = 0; jj < 4; jj++) b_nrow[jj] = wc * 64 + (jj * 2 + (lmat_id >> 1)) * 8 + lmat_m;
    int a_koff = (lmat_id >> 1) * 8;
    int b_koff = (lmat_id & 1) * 8;

#pragma unroll 1
    for (int l = 0; l < 3; l++) {
        // ---- per-layer parameters ----
        const __half* Aop; const __half* W; const float* bias; float* cbuf;
        __half *hOut1; int s1; __half *hOut2; int s2; int K;
        if (l == 0) {
            Aop = g_A0[p]; K = K0;  W = g_W0; bias = g_bias_il;          cbuf = g_c[0];
            hOut1 = g_A1[p];         s1 = K12; hOut2 = g_A0[q] + 2 * D;  s2 = K0;
        } else if (l == 1) {
            Aop = g_A1[p]; K = K12; W = g_W1; bias = g_bias_il + D4;     cbuf = g_c[1];
            hOut1 = g_A2[p];         s1 = K12; hOut2 = g_A1[q] + D;      s2 = K12;
        } else {
            Aop = g_A2[p]; K = K12; W = g_W2; bias = g_bias_il + 2 * D4; cbuf = g_c[2];
            hOut1 = g_A2[q] + D;     s1 = K12; hOut2 = g_A0[q] + D;      s2 = K0;
        }
        int nk = K / BK;

        float acc[2][8][4];
#pragma unroll
        for (int i = 0; i < 2; i++)
#pragma unroll
            for (int j = 0; j < 8; j++)
#pragma unroll
                for (int v = 0; v < 4; v++) acc[i][j][v] = 0.0f;

        auto issue = [&](int st) {
            int buf = st % NSTAGES;
            int kb = st * BK;
            uint32_t abase = smem_u32 + buf * STAGE_HALFS * 2;
            uint32_t bbase = abase + BM * LDA * 2;
#pragma unroll
            for (int ld = 0; ld < 4; ld++) {
                int qq = tid + ld * 256;
                int row = qq >> 3;
                int c8 = (qq & 7) * 8;
                uint32_t saddr = abase + (row * LDA + c8) * 2;
                const __half* g = Aop + (size_t)(bm + row) * K + kb + c8;
                cp_async16(saddr, g, (bm + row < N_NODES) ? 16 : 0);
            }
#pragma unroll
            for (int ld = 0; ld < 4; ld++) {
                int qq = tid + ld * 256;
                int row = qq >> 3;
                int c8 = (qq & 7) * 8;
                uint32_t saddr = bbase + (row * LDA + c8) * 2;
                cp_async16(saddr, W + (size_t)(bn + row) * K + kb + c8, 16);
            }
            asm volatile("cp.async.commit_group;");
        };

        issue(0);
        issue(1);
        asm volatile("cp.async.wait_group 1;");
        __syncthreads();

        uint32_t af[2][2][4];
        uint32_t bf[2][4][4];
        auto load_frags = [&](uint32_t abase, uint32_t bbase, int kk, int pp) {
#pragma unroll
            for (int ii = 0; ii < 2; ii++)
                ldmatrix_x4(af[pp][ii][0], af[pp][ii][1], af[pp][ii][2], af[pp][ii][3],
                            abase + (a_mrow[ii] * LDA + kk + a_koff) * 2);
#pragma unroll
            for (int jj = 0; jj < 4; jj++)
                ldmatrix_x4(bf[pp][jj][0], bf[pp][jj][1], bf[pp][jj][2], bf[pp][jj][3],
                            bbase + (b_nrow[jj] * LDA + kk + b_koff) * 2);
        };

#pragma unroll 1
        for (int i = 0; i < nk; i++) {
            bool more = (i + 2 < nk);
            if (more) issue(i + 2);

            int buf = i % NSTAGES;
            uint32_t abase = smem_u32 + buf * STAGE_HALFS * 2;
            uint32_t bbase = abase + BM * LDA * 2;

            load_frags(abase, bbase, 0, 0);
#pragma unroll
            for (int kk = 0; kk < BK; kk += 16) {
                int pp = (kk >> 4) & 1;
                if (kk + 16 < BK) load_frags(abase, bbase, kk + 16, pp ^ 1);
#pragma unroll
                for (int ii = 0; ii < 2; ii++)
#pragma unroll
                    for (int j = 0; j < 8; j++) {
                        uint32_t b0 = bf[pp][j >> 1][(j & 1) * 2 + 0];
                        uint32_t b1 = bf[pp][j >> 1][(j & 1) * 2 + 1];
                        asm volatile(
                            "mma.sync.aligned.m16n8k16.row.col.f32.f16.f16.f32 "
                            "{%0,%1,%2,%3}, {%4,%5,%6,%7}, {%8,%9}, {%0,%1,%2,%3};"
                            : "+f"(acc[ii][j][0]), "+f"(acc[ii][j][1]),
                              "+f"(acc[ii][j][2]), "+f"(acc[ii][j][3])
                            : "r"(af[pp][ii][0]), "r"(af[pp][ii][1]),
                              "r"(af[pp][ii][2]), "r"(af[pp][ii][3]),
                              "r"(b0), "r"(b1));
                    }
            }
            if (more) { asm volatile("cp.async.wait_group 1;"); }
            else      { asm volatile("cp.async.wait_group 0;"); }
            __syncthreads();
        }

        // ---- stage C into smem (reuse pipeline smem) ----
        float* Cs = (float*)smem_raw;           // [BM][BN+4]
        int g = lane >> 2, t = lane & 3;
#pragma unroll
        for (int i = 0; i < 2; i++)
#pragma unroll
            for (int j = 0; j < 8; j++) {
                int row = wr * 32 + i * 16 + g;
                int col = wc * 64 + j * 8 + t * 2;
                *reinterpret_cast<float2*>(&Cs[row * (BN + 4) + col]) =
                    make_float2(acc[i][j][0], acc[i][j][1]);
                *reinterpret_cast<float2*>(&Cs[(row + 8) * (BN + 4) + col]) =
                    make_float2(acc[i][j][2], acc[i][j][3]);
            }
        __syncthreads();

        // ---- fused LSTM cell epilogue ----
        int row = tid >> 1;
        int node = bm + row;
        if (node < N_NODES) {
            int f0 = (tid & 1) * 16;
            int fg0 = (bn >> 2) + f0;
            float cvals[16];
#pragma unroll
            for (int q4 = 0; q4 < 4; q4++) {
                float4 cv = *reinterpret_cast<float4*>(&cbuf[node * D + fg0 + q4 * 4]);
                cvals[q4 * 4 + 0] = cv.x; cvals[q4 * 4 + 1] = cv.y;
                cvals[q4 * 4 + 2] = cv.z; cvals[q4 * 4 + 3] = cv.w;
            }
            __align__(16) __half hbuf[16];
#pragma unroll
            for (int tt = 0; tt < 16; tt++) {
                int fl = f0 + tt;
                float4 gv = *reinterpret_cast<const float4*>(&Cs[row * (BN + 4) + fl * 4]);
                float4 bb = *reinterpret_cast<const float4*>(&bias[bn + fl * 4]);
                float ig = sigmoidf_(gv.x + bb.x);
                float fg = sigmoidf_(gv.y + bb.y);
                float gg = tanhf(gv.z + bb.z);
                float og = sigmoidf_(gv.w + bb.w);
                float cn = fg * cvals[tt] + ig * gg;
                cvals[tt] = cn;
                hbuf[tt] = __float2half_rn(og * tanhf(cn));
            }
#pragma unroll
            for (int q4 = 0; q4 < 4; q4++) {
                *reinterpret_cast<float4*>(&cbuf[node * D + fg0 + q4 * 4]) =
                    make_float4(cvals[q4 * 4 + 0], cvals[q4 * 4 + 1],
                                cvals[q4 * 4 + 2], cvals[q4 * 4 + 3]);
            }
            uint4* hw = reinterpret_cast<uint4*>(hbuf);
            *reinterpret_cast<uint4*>(&hOut1[node * s1 + fg0]) = hw[0];
            *reinterpret_cast<uint4*>(&hOut1[node * s1 + fg0 + 8]) = hw[1];
            *reinterpret_cast<uint4*>(&hOut2[node * s2 + fg0]) = hw[0];
            *reinterpret_cast<uint4*>(&hOut2[node * s2 + fg0 + 8]) = hw[1];
        }

        // ---- row-local barrier among the 4 column-CTAs of this row group ----
        if (l < 2) {
            __threadfence();
            __syncthreads();
            if (tid == 0) {
                int* ctr = &g_lsync[blockIdx.y * 2 + l];
                atomicAdd(ctr, 1);
                while (atomicAdd(ctr, 0) < 4) __nanosleep(64);
            }
            __syncthreads();
            __threadfence();
        }
    }
}

// ----------------------------------------------------------------------------
// out[n] = h2[n,:] . W_out + b_out   (h2 fp16)
// ----------------------------------------------------------------------------
__global__ void out_kernel(const __half* __restrict__ h2base,
                           const float* __restrict__ W_out,
                           const float* __restrict__ b_out,
                           float* __restrict__ out) {
    int warp = (blockIdx.x * blockDim.x + threadIdx.x) >> 5;
    int lane = threadIdx.x & 31;
    if (warp >= N_NODES) return;
    const __half* h2 = &h2base[warp * K12];
    float s = 0.0f;
#pragma unroll
    for (int i = 0; i < 4; i++)
        s += __half2float(h2[lane + 32 * i]) * W_out[lane + 32 * i];
#pragma unroll
    for (int off = 16; off; off >>= 1) s += __shfl_xor_sync(0xFFFFFFFFu, s, off);
    if (lane == 0) out[warp] = s + b_out[0];
}

// ----------------------------------------------------------------------------
// Launch
// ----------------------------------------------------------------------------
extern "C" void kernel_launch(void* const* d_in, const int* in_sizes, int n_in,
                              void* d_out, int out_size) {
    const float* features = (const float*)d_in[0];
    const int*   src      = (const int*)d_in[1];
    const int*   dst      = (const int*)d_in[2];
    const float* W_in     = (const float*)d_in[3];
    const float* b_in     = (const float*)d_in[4];
    const float* Wih0     = (const float*)d_in[5];
    const float* Wih_rest = (const float*)d_in[6];
    const float* Whh      = (const float*)d_in[7];
    const float* bih      = (const float*)d_in[8];
    const float* bhh      = (const float*)d_in[9];
    const float* W_out    = (const float*)d_in[10];
    const float* b_out    = (const float*)d_in[11];
    float* out = (float*)d_out;

    static __half *A2base = nullptr;
    if (!A2base) {
        cudaGetSymbolAddress((void**)&A2base, g_A2);
    }
    cudaFuncSetAttribute(step3_kernel,
                         cudaFuncAttributeMaxDynamicSharedMemorySize, SMEM_BYTES);

    zero_all_kernel<<<592, 256>>>();
    build_all_kernel<<<(BUILD_TOTAL + 255) / 256, 256>>>(Wih0, Wih_rest, Whh, bih, bhh);
    init_feat_kernel<<<(N_NODES * D + 255) / 256, 256>>>(features, W_in, b_in);
    count_deg_kernel<<<(N_EDGES + 255) / 256, 256>>>(dst);
    scan_deg_kernel<<<1, 1024>>>();
    fill_csr_kernel<<<(N_EDGES + 255) / 256, 256>>>(src, dst);

    dim3 step_grid(D4 / BN, MGROUPS);   // (4, 157): column blocks fastest
    int agg_blocks = (N_NODES * 32 + 255) / 256;

    for (int s = 0; s < STEPS; s++) {
        int p = s & 1;
        agg_kernel<<<agg_blocks, 256>>>(p);
        step3_kernel<<<step_grid, 256, SMEM_BYTES>>>(p);
    }

    // final h2 lives in g_A2[STEPS & 1] cols [D, 2D)
    out_kernel<<<(N_NODES * 32 + 255) / 256, 256>>>(
        A2base + (size_t)(STEPS & 1) * N_NODES * K12 + D, W_out, b_out, out);
}

// round 17
// speedup vs baseline: 1.1711x; 1.1711x over previous
#include <cuda_runtime.h>
#include <cuda_fp16.h>
#include <math.h>
#include <stdint.h>

#define N_NODES 20000
#define N_EDGES 640000
#define FDIM 6
#define D 128
#define D4 512
#define STEPS 11          // 1 + DEPTH
#define K0 384            // layer0 K: agg(128)+feat(128)+h0(128)
#define K12 256           // layers 1,2 K: h_prev(128)+h_self(128)

#define BM 128
#define BN 64
#define BK 64
#define NSTAGES 2
#define LDA (BK + 8)              // 72 halfs: 144B row stride (16B multiple)
#define STAGE_HALFS ((BM + BN) * LDA)                 // 13824 halfs
#define SMEM_BYTES (NSTAGES * STAGE_HALFS * 2)        // 55296 > C staging 34816

// ----------------------------------------------------------------------------
// Scratch (device globals; ping-pong parity buffers; activations in fp16)
// ----------------------------------------------------------------------------
__device__ __half g_A0[2][N_NODES * K0];    // [agg | feat | h0]
__device__ __half g_A1[2][N_NODES * K12];   // [h0 | h1]
__device__ __half g_A2[2][N_NODES * K12];   // [h1 | h2]
__device__ float  g_c[3][N_NODES * D];
__device__ __half g_W0[D4 * K0];            // interleaved-gate rows, fp16
__device__ __half g_W1[D4 * K12];
__device__ __half g_W2[D4 * K12];
__device__ float  g_bias_il[3 * D4];        // interleaved (bih+bhh)
__device__ int    g_deg[N_NODES];
__device__ int    g_rowstart[N_NODES + 1];
__device__ int    g_cursor[N_NODES];
__device__ int    g_csr[N_EDGES];

// ----------------------------------------------------------------------------
// Init / preprocessing
// ----------------------------------------------------------------------------
__global__ void zero_all_kernel() {
    int idx = blockIdx.x * blockDim.x + threadIdx.x;
    int stride = gridDim.x * blockDim.x;
    int* a0 = (int*)&g_A0[0][0];
    int* a1 = (int*)&g_A1[0][0];
    int* a2 = (int*)&g_A2[0][0];
    for (int i = idx; i < N_NODES * K0 / 2; i += stride)  a0[i] = 0;
    for (int i = idx; i < N_NODES * K12 / 2; i += stride) a1[i] = 0;
    for (int i = idx; i < N_NODES * K12 / 2; i += stride) a2[i] = 0;
    for (int i = idx; i < 3 * N_NODES * D; i += stride) (&g_c[0][0])[i] = 0.0f;
    for (int i = idx; i < N_NODES; i += stride) { g_deg[i] = 0; g_cursor[i] = 0; }
}

// One kernel builds all interleaved fp16 weights + combined bias.
// Interleave: row r = 4*d + g  <-  old row g*128+d; K = [Wih | Whh]
__device__ __forceinline__ void build_one_w(__half* dst, const float* Wih,
                                            const float* Whh, int Kin, int idx) {
    int K = Kin + D;
    int r = idx / K, k = idx % K;
    int d = r >> 2, g = r & 3;
    int orow = g * D + d;
    float v = (k < Kin) ? Wih[orow * Kin + k] : Whh[orow * D + (k - Kin)];
    dst[idx] = __float2half_rn(v);
}

__global__ void build_all_kernel(const float* __restrict__ Wih0,
                                 const float* __restrict__ Wih_rest,
                                 const float* __restrict__ Whh,
                                 const float* __restrict__ bih,
                                 const float* __restrict__ bhh) {
    const int N0 = D4 * K0;             // 196608
    const int N1 = D4 * K12;            // 131072
    int idx = blockIdx.x * blockDim.x + threadIdx.x;
    if (idx < N0) {
        build_one_w(g_W0, Wih0, Whh, 2 * D, idx);
    } else if (idx < N0 + N1) {
        build_one_w(g_W1, Wih_rest, Whh + D4 * D, D, idx - N0);
    } else if (idx < N0 + 2 * N1) {
        build_one_w(g_W2, Wih_rest + D4 * D, Whh + 2 * D4 * D, D, idx - N0 - N1);
    } else if (idx < N0 + 2 * N1 + 3 * D4) {
        int i = idx - N0 - 2 * N1;
        int l = i >> 9, r = i & 511;
        int d = r >> 2, g = r & 3;
        int o = l * D4 + g * D + d;
        g_bias_il[i] = bih[o] + bhh[o];
    }
}
#define BUILD_TOTAL (D4 * K0 + 2 * D4 * K12 + 3 * D4)

// feat = relu(features @ W_in + b_in) -> g_A0[0] cols [128,256), fp16
__global__ void init_feat_kernel(const float* __restrict__ features,
                                 const float* __restrict__ W_in,
                                 const float* __restrict__ b_in) {
    __shared__ float sW[FDIM * D];
    __shared__ float sb[D];
    int t = threadIdx.x;
    for (int i = t; i < FDIM * D; i += blockDim.x) sW[i] = W_in[i];
    for (int i = t; i < D; i += blockDim.x) sb[i] = b_in[i];
    __syncthreads();
    int idx = blockIdx.x * blockDim.x + t;
    if (idx >= N_NODES * D) return;
    int n = idx >> 7;
    int d = idx & (D - 1);
    float acc = sb[d];
#pragma unroll
    for (int f = 0; f < FDIM; f++) acc += features[n * FDIM + f] * sW[f * D + d];
    g_A0[0][n * K0 + D + d] = __float2half_rn(fmaxf(acc, 0.0f));
}

__global__ void count_deg_kernel(const int* __restrict__ dst) {
    int e = blockIdx.x * blockDim.x + threadIdx.x;
    if (e < N_EDGES) atomicAdd(&g_deg[dst[e]], 1);
}

__global__ void scan_deg_kernel() {
    __shared__ int sh[1024];
    int t = threadIdx.x;
    int carry = 0;
    for (int base = 0; base < N_NODES; base += 1024) {
        int v = (base + t < N_NODES) ? g_deg[base + t] : 0;
        sh[t] = v;
        __syncthreads();
        for (int off = 1; off < 1024; off <<= 1) {
            int x = (t >= off) ? sh[t - off] : 0;
            __syncthreads();
            sh[t] += x;
            __syncthreads();
        }
        if (base + t < N_NODES) g_rowstart[base + t] = carry + sh[t] - v;
        int blocktotal = sh[1023];
        __syncthreads();
        carry += blocktotal;
    }
    if (t == 0) g_rowstart[N_NODES] = carry;
}

__global__ void fill_csr_kernel(const int* __restrict__ src,
                                const int* __restrict__ dst) {
    int e = blockIdx.x * blockDim.x + threadIdx.x;
    if (e < N_EDGES) {
        int d = dst[e];
        int pos = atomicAdd(&g_cursor[d], 1);
        g_csr[g_rowstart[d] + pos] = src[e];
    }
}

// ----------------------------------------------------------------------------
// Mean aggregation (fp16 in/out, fp32 accum): one warp per node, 4-edge unroll
// ----------------------------------------------------------------------------
__global__ void agg_kernel(const __half* __restrict__ A0r, __half* __restrict__ A0w) {
    int warp = (blockIdx.x * blockDim.x + threadIdx.x) >> 5;
    int lane = threadIdx.x & 31;
    if (warp >= N_NODES) return;
    int s0 = g_rowstart[warp];
    int s1 = g_rowstart[warp + 1];
    float ax = 0.f, ay = 0.f, az = 0.f, aw = 0.f;
    int coff = D + lane * 4;
    int e = s0;
    for (; e + 4 <= s1; e += 4) {
        int n0 = g_csr[e + 0];
        int n1 = g_csr[e + 1];
        int n2 = g_csr[e + 2];
        int n3 = g_csr[e + 3];
        uint2 r0 = *reinterpret_cast<const uint2*>(&A0r[(size_t)n0 * K0 + coff]);
        uint2 r1 = *reinterpret_cast<const uint2*>(&A0r[(size_t)n1 * K0 + coff]);
        uint2 r2 = *reinterpret_cast<const uint2*>(&A0r[(size_t)n2 * K0 + coff]);
        uint2 r3 = *reinterpret_cast<const uint2*>(&A0r[(size_t)n3 * K0 + coff]);
#pragma unroll
        for (int q = 0; q < 4; q++) {
            uint2 rr = (q == 0) ? r0 : (q == 1) ? r1 : (q == 2) ? r2 : r3;
            __half2 p0 = *reinterpret_cast<__half2*>(&rr.x);
            __half2 p1 = *reinterpret_cast<__half2*>(&rr.y);
            float2 f0 = __half22float2(p0);
            float2 f1 = __half22float2(p1);
            ax += f0.x; ay += f0.y; az += f1.x; aw += f1.y;
        }
    }
    for (; e < s1; e++) {
        int s = g_csr[e];
        uint2 raw = *reinterpret_cast<const uint2*>(&A0r[(size_t)s * K0 + coff]);
        __half2 p0 = *reinterpret_cast<__half2*>(&raw.x);
        __half2 p1 = *reinterpret_cast<__half2*>(&raw.y);
        float2 f0 = __half22float2(p0);
        float2 f1 = __half22float2(p1);
        ax += f0.x; ay += f0.y; az += f1.x; aw += f1.y;
    }
    float inv = (s1 > s0) ? 1.0f / (float)(s1 - s0) : 0.0f;
    __half2 o0 = __floats2half2_rn(ax * inv, ay * inv);
    __half2 o1 = __floats2half2_rn(az * inv, aw * inv);
    uint2 outw;
    outw.x = *reinterpret_cast<uint32_t*>(&o0);
    outw.y = *reinterpret_cast<uint32_t*>(&o1);
    *reinterpret_cast<uint2*>(&A0w[warp * K0 + lane * 4]) = outw;
}

// ----------------------------------------------------------------------------
// Fused GEMM (fp16 mma, 2-stage cp.async, occupancy 3) + LSTM cell epilogue
// BM=128, BN=64: acc 32 regs/thread -> fits 85-reg cap of occ=3.
// ----------------------------------------------------------------------------
__device__ __forceinline__ float sigmoidf_(float x) { return 1.0f / (1.0f + expf(-x)); }

__device__ __forceinline__ void cp_async16(uint32_t saddr, const void* gaddr, int srcsize) {
    asm volatile("cp.async.cg.shared.global [%0], [%1], 16, %2;"
                 :: "r"(saddr), "l"(gaddr), "r"(srcsize));
}

__device__ __forceinline__ void ldmatrix_x4(uint32_t& r0, uint32_t& r1,
                                            uint32_t& r2, uint32_t& r3,
                                            uint32_t addr) {
    asm volatile("ldmatrix.sync.aligned.m8n8.x4.shared.b16 {%0,%1,%2,%3}, [%4];"
                 : "=r"(r0), "=r"(r1), "=r"(r2), "=r"(r3) : "r"(addr));
}

extern __shared__ __align__(16) char smem_raw[];

__global__ __launch_bounds__(256, 3)
void gemm_lstm_kernel(const __half* __restrict__ Aop, int K,
                      const __half* __restrict__ W,
                      const float* __restrict__ bias,
                      float* __restrict__ cbuf,
                      __half* __restrict__ hOut1, int s1,
                      __half* __restrict__ hOut2, int s2) {
    int tid = threadIdx.x;
    int lane = tid & 31, warp = tid >> 5;
    int wr = warp >> 1, wc = warp & 1;          // warp grid 4(m) x 2(n)
    int bm = blockIdx.x * BM, bn = blockIdx.y * BN;
    uint32_t smem_u32 = (uint32_t)__cvta_generic_to_shared(smem_raw);

    float acc[2][4][4];
#pragma unroll
    for (int i = 0; i < 2; i++)
#pragma unroll
        for (int j = 0; j < 4; j++)
#pragma unroll
            for (int v = 0; v < 4; v++) acc[i][j][v] = 0.0f;

    int lmat_m = lane & 7;
    int lmat_id = lane >> 3;
    int nk = K / BK;

    int a_mrow[2], b_nrow[2];
#pragma unroll
    for (int ii = 0; ii < 2; ii++) a_mrow[ii] = wr * 32 + ii * 16 + (lmat_id & 1) * 8 + lmat_m;
#pragma unroll
    for (int jj = 0; jj < 2; jj++) b_nrow[jj] = wc * 32 + (jj * 2 + (lmat_id >> 1)) * 8 + lmat_m;
    int a_koff = (lmat_id >> 1) * 8;
    int b_koff = (lmat_id & 1) * 8;

    // stage issue: A[128xBK] + B[64xBK] for k-block `st` into buffer st&1
    auto issue = [&](int st) {
        int buf = st & 1;
        int kb = st * BK;
        uint32_t abase = smem_u32 + buf * STAGE_HALFS * 2;
        uint32_t bbase = abase + BM * LDA * 2;
#pragma unroll
        for (int l = 0; l < 4; l++) {
            int q = tid + l * 256;          // 1024 chunks: 128 rows x 8
            int row = q >> 3;
            int c8 = (q & 7) * 8;
            uint32_t saddr = abase + (row * LDA + c8) * 2;
            const __half* g = Aop + (size_t)(bm + row) * K + kb + c8;
            cp_async16(saddr, g, (bm + row < N_NODES) ? 16 : 0);
        }
#pragma unroll
        for (int l = 0; l < 2; l++) {
            int q = tid + l * 256;          // 512 chunks: 64 rows x 8
            int row = q >> 3;
            int c8 = (q & 7) * 8;
            uint32_t saddr = bbase + (row * LDA + c8) * 2;
            cp_async16(saddr, W + (size_t)(bn + row) * K + kb + c8, 16);
        }
        asm volatile("cp.async.commit_group;");
    };

    issue(0);
    issue(1);

#pragma unroll 1
    for (int i = 0; i < nk; i++) {
        if (i + 1 < nk) { asm volatile("cp.async.wait_group 1;"); }
        else            { asm volatile("cp.async.wait_group 0;"); }
        __syncthreads();

        int buf = i & 1;
        uint32_t abase = smem_u32 + buf * STAGE_HALFS * 2;
        uint32_t bbase = abase + BM * LDA * 2;
#pragma unroll
        for (int kk = 0; kk < BK; kk += 16) {
            uint32_t af[2][4];
            uint32_t bf[2][4];
#pragma unroll
            for (int ii = 0; ii < 2; ii++)
                ldmatrix_x4(af[ii][0], af[ii][1], af[ii][2], af[ii][3],
                            abase + (a_mrow[ii] * LDA + kk + a_koff) * 2);
#pragma unroll
            for (int jj = 0; jj < 2; jj++)
                ldmatrix_x4(bf[jj][0], bf[jj][1], bf[jj][2], bf[jj][3],
                            bbase + (b_nrow[jj] * LDA + kk + b_koff) * 2);
#pragma unroll
            for (int ii = 0; ii < 2; ii++)
#pragma unroll
                for (int j = 0; j < 4; j++) {
                    uint32_t b0 = bf[j >> 1][(j & 1) * 2 + 0];
                    uint32_t b1 = bf[j >> 1][(j & 1) * 2 + 1];
                    asm volatile(
                        "mma.sync.aligned.m16n8k16.row.col.f32.f16.f16.f32 "
                        "{%0,%1,%2,%3}, {%4,%5,%6,%7}, {%8,%9}, {%0,%1,%2,%3};"
                        : "+f"(acc[ii][j][0]), "+f"(acc[ii][j][1]),
                          "+f"(acc[ii][j][2]), "+f"(acc[ii][j][3])
                        : "r"(af[ii][0]), "r"(af[ii][1]), "r"(af[ii][2]), "r"(af[ii][3]),
                          "r"(b0), "r"(b1));
                }
        }
        __syncthreads();
        if (i + 2 < nk) issue(i + 2);
    }

    // ---- stage C into smem (reuse pipeline smem; all reads complete) ----
    float* Cs = (float*)smem_raw;           // [BM][BN+4]
    int g = lane >> 2, t = lane & 3;
#pragma unroll
    for (int i = 0; i < 2; i++)
#pragma unroll
        for (int j = 0; j < 4; j++) {
            int row = wr * 32 + i * 16 + g;
            int col = wc * 32 + j * 8 + t * 2;
            *reinterpret_cast<float2*>(&Cs[row * (BN + 4) + col]) =
                make_float2(acc[i][j][0], acc[i][j][1]);
            *reinterpret_cast<float2*>(&Cs[(row + 8) * (BN + 4) + col]) =
                make_float2(acc[i][j][2], acc[i][j][3]);
        }
    __syncthreads();

    // ---- fused LSTM cell epilogue: 2 threads per row, 8 features each ----
    int row = tid >> 1;
    int node = bm + row;
    if (node < N_NODES) {
        int f0 = (tid & 1) * 8;
        int fg0 = (bn >> 2) + f0;
        float4 c0 = *reinterpret_cast<float4*>(&cbuf[node * D + fg0]);
        float4 c1 = *reinterpret_cast<float4*>(&cbuf[node * D + fg0 + 4]);
        float cv[8] = {c0.x, c0.y, c0.z, c0.w, c1.x, c1.y, c1.z, c1.w};
        __align__(16) __half hbuf[8];
#pragma unroll
        for (int tt = 0; tt < 8; tt++) {
            int fl = f0 + tt;
            float4 gv = *reinterpret_cast<const float4*>(&Cs[row * (BN + 4) + fl * 4]);
            float4 bb = *reinterpret_cast<const float4*>(&bias[bn + fl * 4]);
            float ig = sigmoidf_(gv.x + bb.x);
            float fg = sigmoidf_(gv.y + bb.y);
            float gg = tanhf(gv.z + bb.z);
            float og = sigmoidf_(gv.w + bb.w);
            float cn = fg * cv[tt] + ig * gg;
            cv[tt] = cn;
            hbuf[tt] = __float2half_rn(og * tanhf(cn));
        }
        *reinterpret_cast<float4*>(&cbuf[node * D + fg0]) =
            make_float4(cv[0], cv[1], cv[2], cv[3]);
        *reinterpret_cast<float4*>(&cbuf[node * D + fg0 + 4]) =
            make_float4(cv[4], cv[5], cv[6], cv[7]);
        uint4 hw = *reinterpret_cast<uint4*>(hbuf);
        *reinterpret_cast<uint4*>(&hOut1[node * s1 + fg0]) = hw;
        *reinterpret_cast<uint4*>(&hOut2[node * s2 + fg0]) = hw;
    }
}

// ----------------------------------------------------------------------------
// out[n] = h2[n,:] . W_out + b_out   (h2 fp16)
// ----------------------------------------------------------------------------
__global__ void out_kernel(const __half* __restrict__ h2base,
                           const float* __restrict__ W_out,
                           const float* __restrict__ b_out,
                           float* __restrict__ out) {
    int warp = (blockIdx.x * blockDim.x + threadIdx.x) >> 5;
    int lane = threadIdx.x & 31;
    if (warp >= N_NODES) return;
    const __half* h2 = &h2base[warp * K12];
    float s = 0.0f;
#pragma unroll
    for (int i = 0; i < 4; i++)
        s += __half2float(h2[lane + 32 * i]) * W_out[lane + 32 * i];
#pragma unroll
    for (int off = 16; off; off >>= 1) s += __shfl_xor_sync(0xFFFFFFFFu, s, off);
    if (lane == 0) out[warp] = s + b_out[0];
}

// ----------------------------------------------------------------------------
// Launch
// ----------------------------------------------------------------------------
extern "C" void kernel_launch(void* const* d_in, const int* in_sizes, int n_in,
                              void* d_out, int out_size) {
    const float* features = (const float*)d_in[0];
    const int*   src      = (const int*)d_in[1];
    const int*   dst      = (const int*)d_in[2];
    const float* W_in     = (const float*)d_in[3];
    const float* b_in     = (const float*)d_in[4];
    const float* Wih0     = (const float*)d_in[5];
    const float* Wih_rest = (const float*)d_in[6];
    const float* Whh      = (const float*)d_in[7];
    const float* bih      = (const float*)d_in[8];
    const float* bhh      = (const float*)d_in[9];
    const float* W_out    = (const float*)d_in[10];
    const float* b_out    = (const float*)d_in[11];
    float* out = (float*)d_out;

    static __half *A0p[2] = {nullptr, nullptr}, *A1p[2], *A2p[2];
    static float *cp[3];
    static float *biasp;
    static __half *W0p, *W1p, *W2p;
    if (!A0p[0]) {
        cudaGetSymbolAddress((void**)&A0p[0], g_A0);
        A0p[1] = A0p[0] + N_NODES * K0;
        cudaGetSymbolAddress((void**)&A1p[0], g_A1);
        A1p[1] = A1p[0] + N_NODES * K12;
        cudaGetSymbolAddress((void**)&A2p[0], g_A2);
        A2p[1] = A2p[0] + N_NODES * K12;
        cudaGetSymbolAddress((void**)&cp[0], g_c);
        cp[1] = cp[0] + N_NODES * D;
        cp[2] = cp[1] + N_NODES * D;
        cudaGetSymbolAddress((void**)&biasp, g_bias_il);
        cudaGetSymbolAddress((void**)&W0p, g_W0);
        cudaGetSymbolAddress((void**)&W1p, g_W1);
        cudaGetSymbolAddress((void**)&W2p, g_W2);
    }
    cudaFuncSetAttribute(gemm_lstm_kernel,
                         cudaFuncAttributeMaxDynamicSharedMemorySize, SMEM_BYTES);

    zero_all_kernel<<<592, 256>>>();
    build_all_kernel<<<(BUILD_TOTAL + 255) / 256, 256>>>(Wih0, Wih_rest, Whh, bih, bhh);
    init_feat_kernel<<<(N_NODES * D + 255) / 256, 256>>>(features, W_in, b_in);
    count_deg_kernel<<<(N_EDGES + 255) / 256, 256>>>(dst);
    scan_deg_kernel<<<1, 1024>>>();
    fill_csr_kernel<<<(N_EDGES + 255) / 256, 256>>>(src, dst);

    dim3 gemm_grid((N_NODES + BM - 1) / BM, D4 / BN);   // 157 x 8
    int agg_blocks = (N_NODES * 32 + 255) / 256;

    for (int s = 0; s < STEPS; s++) {
        int p = s & 1, q = p ^ 1;
        agg_kernel<<<agg_blocks, 256>>>(A0p[p], A0p[p]);
        // layer0: reads A0[p]; h0 -> A1[p][0,D) and A0[q][2D,3D)
        gemm_lstm_kernel<<<gemm_grid, 256, SMEM_BYTES>>>(A0p[p], K0, W0p, biasp, cp[0],
                                                         A1p[p], K12, A0p[q] + 2 * D, K0);
        // layer1: reads A1[p]; h1 -> A2[p][0,D) and A1[q][D,2D)
        gemm_lstm_kernel<<<gemm_grid, 256, SMEM_BYTES>>>(A1p[p], K12, W1p, biasp + D4, cp[1],
                                                         A2p[p], K12, A1p[q] + D, K12);
        // layer2: reads A2[p]; h2 -> A2[q][D,2D) and A0[q][D,2D) (next feat)
        gemm_lstm_kernel<<<gemm_grid, 256, SMEM_BYTES>>>(A2p[p], K12, W2p, biasp + 2 * D4, cp[2],
                                                         A2p[q] + D, K12, A0p[q] + D, K0);
    }

    out_kernel<<<(N_NODES * 32 + 255) / 256, 256>>>(A2p[STEPS & 1] + D, W_out, b_out, out);
}